// round 5
// baseline (speedup 1.0000x reference)
#include <cuda_runtime.h>
#include <math.h>

#define B_     2
#define C_     128
#define HW_    36864
#define N_     73728
#define E_     4
#define HID_   340
#define NCHW_  9437184

typedef unsigned long long u64;

__device__ __forceinline__ u64 fma2(u64 a, u64 b, u64 c) {
    u64 d; asm("fma.rn.f32x2 %0, %1, %2, %3;" : "=l"(d) : "l"(a), "l"(b), "l"(c)); return d;
}
__device__ __forceinline__ u64 dup2(float x) {
    u64 d; asm("mov.b64 %0, {%1, %1};" : "=l"(d) : "f"(x)); return d;
}
__device__ __forceinline__ float2 unpack2(u64 a) {
    float2 r; asm("mov.b64 {%0, %1}, %2;" : "=f"(r.x), "=f"(r.y) : "l"(a)); return r;
}
__device__ __forceinline__ float gelu_exact(float v) {
    return 0.5f * v * (1.0f + erff(v * 0.70710678118654752440f));
}

// ----------------------------- device scratch -----------------------------
__device__ float g_emb[B_ * C_];
__device__ float g_WbT[B_ * C_ * C_];          // [b][c][o]
__device__ float g_ty[(size_t)N_ * C_];        // conv-out tokens [n][c]
__device__ int   g_cnt[E_];
__device__ int   g_tok[E_ * N_];
__device__ float g_gate[E_ * N_];
__device__ int   g_slot[N_ * 2];
__device__ float g_obuf[(size_t)E_ * N_ * C_]; // gated expert outputs per slot

// ----------------------------- K1: channel means -----------------------------
__global__ void k_mean(const float* __restrict__ x) {
    int row = blockIdx.x;                   // b*C + c
    int t = threadIdx.x;
    const float4* xr = (const float4*)(x + (size_t)row * HW_);
    float s = 0.f;
    for (int i = t; i < HW_ / 4; i += 256) {
        float4 v = xr[i];
        s += (v.x + v.y) + (v.z + v.w);
    }
    __shared__ float sm[256];
    sm[t] = s; __syncthreads();
    for (int o = 128; o > 0; o >>= 1) {
        if (t < o) sm[t] += sm[t + o];
        __syncthreads();
    }
    if (t == 0) g_emb[row] = sm[0] * (1.0f / (float)HW_);
}

// --------------------- K2: prompt softmax + fold conv W ---------------------
__global__ void k_prep(const float* __restrict__ prompt, const float* __restrict__ w_lin,
                       const float* __restrict__ b_lin, const float* __restrict__ w_conv) {
    int t = threadIdx.x;
    __shared__ float s_l[B_ * 5], s_pw[B_ * 5], s_sp[B_ * C_];
    if (t < E_) g_cnt[t] = 0;               // reset routing counters every launch
    if (t < B_ * 5) {
        int b = t / 5, p = t % 5;
        float a = b_lin[p];
        for (int c = 0; c < C_; c++) a += g_emb[b * C_ + c] * w_lin[p * C_ + c];
        s_l[t] = a;
    }
    __syncthreads();
    if (t < B_) {
        float m = s_l[t * 5];
        for (int p = 1; p < 5; p++) m = fmaxf(m, s_l[t * 5 + p]);
        float e[5]; float den = 0.f;
        for (int p = 0; p < 5; p++) { e[p] = expf(s_l[t * 5 + p] - m); den += e[p]; }
        for (int p = 0; p < 5; p++) s_pw[t * 5 + p] = e[p] / den;
    }
    __syncthreads();
    {
        int b = t >> 7, c = t & 127;
        float a = 0.f;
        for (int p = 0; p < 5; p++) a += s_pw[b * 5 + p] * prompt[p * C_ + c];
        s_sp[t] = a;
    }
    __syncthreads();
    for (int i = t; i < B_ * C_ * C_; i += 256) {
        int b = i >> 14; int rem = i & 16383; int c = rem >> 7; int o = rem & 127;
        g_WbT[i] = w_conv[o * C_ + c] * s_sp[b * C_ + c];
    }
}

// ---------------- K3: 1x1 conv + gating + top-2 routing scatter ----------------
__global__ void __launch_bounds__(256) k_conv_gate(const float* __restrict__ x,
                                                   const float* __restrict__ w_gate) {
    __shared__ __align__(16) float s_x[C_ * 66];
    __shared__ float s_lg[64 * 4];
    int t = threadIdx.x;
    int n0 = blockIdx.x * 64;
    int b = n0 / HW_; int hw0 = n0 % HW_;
    const float* xb = x + (size_t)b * C_ * HW_ + hw0;
    for (int i = t; i < C_ * 64; i += 256) {
        int c = i >> 6, tk = i & 63;
        s_x[c * 66 + tk] = xb[(size_t)c * HW_ + tk];
    }
    __syncthreads();
    {   // gating logits: thread = (expert, token)
        int e = t >> 6, tk = t & 63;
        float a = 0.f;
        #pragma unroll 8
        for (int c = 0; c < C_; c++) a += s_x[c * 66 + tk] * w_gate[c * 4 + e];
        s_lg[tk * 4 + e] = a;
    }
    __syncthreads();
    if (t < 64) {       // top-2 + softmax + scatter
        float l[4];
        #pragma unroll
        for (int e = 0; e < 4; e++) l[e] = s_lg[t * 4 + e];
        int e0 = 0; float m0 = l[0];
        #pragma unroll
        for (int e = 1; e < 4; e++) if (l[e] > m0) { m0 = l[e]; e0 = e; }
        int e1 = (e0 == 0) ? 1 : 0; float m1 = l[e1];
        #pragma unroll
        for (int e = 0; e < 4; e++) if (e != e0 && l[e] > m1) { m1 = l[e]; e1 = e; }
        float ex = expf(m1 - m0);
        float g0 = 1.0f / (1.0f + ex);
        float g1 = ex * g0;
        int n = n0 + t;
        int p0 = atomicAdd(&g_cnt[e0], 1);
        g_tok[e0 * N_ + p0] = n; g_gate[e0 * N_ + p0] = g0;
        g_slot[n * 2 + 0] = e0 * N_ + p0;
        int p1 = atomicAdd(&g_cnt[e1], 1);
        g_tok[e1 * N_ + p1] = n; g_gate[e1 * N_ + p1] = g1;
        g_slot[n * 2 + 1] = e1 * N_ + p1;
    }
    // conv GEMM: ty[tok][o] = sum_c s_x[c][tok] * WbT[b][c][o]
    int warp = t >> 5, lane = t & 31, tokb = warp * 8;
    u64 acc[4][4];
    #pragma unroll
    for (int p = 0; p < 4; p++)
        #pragma unroll
        for (int j = 0; j < 4; j++) acc[p][j] = 0ull;
    const float* wr = g_WbT + b * C_ * C_ + lane * 4;
    #pragma unroll 4
    for (int c = 0; c < C_; c++) {
        float4 w = *(const float4*)(wr + c * C_);
        const u64* ap = (const u64*)(s_x + c * 66 + tokb);
        u64 a[4]; a[0] = ap[0]; a[1] = ap[1]; a[2] = ap[2]; a[3] = ap[3];
        u64 d[4]; d[0] = dup2(w.x); d[1] = dup2(w.y); d[2] = dup2(w.z); d[3] = dup2(w.w);
        #pragma unroll
        for (int p = 0; p < 4; p++)
            #pragma unroll
            for (int j = 0; j < 4; j++) acc[p][j] = fma2(a[p], d[j], acc[p][j]);
    }
    #pragma unroll
    for (int p = 0; p < 4; p++) {
        float2 v0 = unpack2(acc[p][0]), v1 = unpack2(acc[p][1]);
        float2 v2 = unpack2(acc[p][2]), v3 = unpack2(acc[p][3]);
        size_t tok0 = (size_t)(n0 + tokb + 2 * p);
        *(float4*)(g_ty + tok0 * C_ + lane * 4)       = make_float4(v0.x, v1.x, v2.x, v3.x);
        *(float4*)(g_ty + (tok0 + 1) * C_ + lane * 4) = make_float4(v0.y, v1.y, v2.y, v3.y);
    }
}

// ---------------- K4: fused expert fc1 + gelu + fc2 (routed) ----------------
// smem: s_ty[128][66] | s_h[128][66] | s_w1[128c][128h] | s_w2[128h][128c] | s_g[64] | s_tk[64]
#define SM_TY 0
#define SM_H  8448
#define SM_W1 16896
#define SM_W2 33280
#define SM_G  49664
#define SM_TK 49728
#define SM_BYTES (49792 * 4)

__global__ void __launch_bounds__(256) k_expert(const float* __restrict__ w1,
                                                const float* __restrict__ b1,
                                                const float* __restrict__ w2,
                                                const float* __restrict__ b2) {
    extern __shared__ __align__(16) float sm[];
    float* s_ty = sm + SM_TY;
    float* s_h  = sm + SM_H;
    float* s_w1 = sm + SM_W1;
    float* s_w2 = sm + SM_W2;
    float* s_g  = sm + SM_G;
    int*   s_tk = (int*)(sm + SM_TK);

    int e = blockIdx.y;
    int cnt = g_cnt[e];
    int start = blockIdx.x * 64;
    if (start >= cnt) return;
    int t = threadIdx.x;
    if (t < 64) {
        int idx = start + t;
        if (idx < cnt) { s_tk[t] = g_tok[e * N_ + idx]; s_g[t] = g_gate[e * N_ + idx]; }
        else           { s_tk[t] = 0;                   s_g[t] = 0.f; }
    }
    __syncthreads();
    // gather ty tile, transposed [c][slot]
    #pragma unroll
    for (int k = 0; k < 8; k++) {
        int lin = t + k * 256; int slot = lin >> 5, c4 = lin & 31;
        int tok = s_tk[slot];
        float4 v = *(const float4*)(g_ty + (size_t)tok * C_ + c4 * 4);
        s_ty[(c4 * 4 + 0) * 66 + slot] = v.x;
        s_ty[(c4 * 4 + 1) * 66 + slot] = v.y;
        s_ty[(c4 * 4 + 2) * 66 + slot] = v.z;
        s_ty[(c4 * 4 + 3) * 66 + slot] = v.w;
    }
    int warp = t >> 5, lane = t & 31, tokb = warp * 8;
    const float* w1e = w1 + e * C_ * HID_;
    const float* w2e = w2 + e * HID_ * C_;
    u64 out[4][4];
    #pragma unroll
    for (int p = 0; p < 4; p++)
        #pragma unroll
        for (int j = 0; j < 4; j++) out[p][j] = 0ull;

    for (int ch = 0; ch < 3; ch++) {
        int hb = ch * 128;
        __syncthreads();                     // prev fc2 done with s_h/s_w2
        for (int i = t; i < 16384; i += 256) {  // stage w1 chunk [c][hh]
            int c = i >> 7, hh = i & 127; int hid = hb + hh;
            s_w1[i] = (hid < HID_) ? w1e[c * HID_ + hid] : 0.f;
        }
        for (int i = t; i < 16384; i += 256) {  // stage w2 chunk [hh][c]
            int hh = i >> 7, c = i & 127; int hid = hb + hh;
            s_w2[i] = (hid < HID_) ? w2e[hid * C_ + c] : 0.f;
        }
        __syncthreads();
        // fc1: lane owns hids h4..h4+3 (within chunk), 4 token-pairs
        int h4 = lane * 4;
        u64 acc[4][4];
        #pragma unroll
        for (int j = 0; j < 4; j++) {
            int hid = hb + h4 + j;
            float bv = (hid < HID_) ? b1[e * HID_ + hid] : 0.f;
            u64 bb = dup2(bv);
            #pragma unroll
            for (int p = 0; p < 4; p++) acc[p][j] = bb;
        }
        #pragma unroll 2
        for (int c = 0; c < C_; c++) {
            const u64* ap = (const u64*)(s_ty + c * 66 + tokb);
            u64 a[4]; a[0] = ap[0]; a[1] = ap[1]; a[2] = ap[2]; a[3] = ap[3];
            float4 w = *(const float4*)(s_w1 + c * 128 + h4);
            u64 d[4]; d[0] = dup2(w.x); d[1] = dup2(w.y); d[2] = dup2(w.z); d[3] = dup2(w.w);
            #pragma unroll
            for (int p = 0; p < 4; p++)
                #pragma unroll
                for (int j = 0; j < 4; j++) acc[p][j] = fma2(a[p], d[j], acc[p][j]);
        }
        // gelu + store h transposed [hid][tok]
        #pragma unroll
        for (int p = 0; p < 4; p++)
            #pragma unroll
            for (int j = 0; j < 4; j++) {
                float2 v = unpack2(acc[p][j]);
                v.x = gelu_exact(v.x); v.y = gelu_exact(v.y);
                *(float2*)(s_h + (h4 + j) * 66 + tokb + 2 * p) = v;
            }
        __syncthreads();
        // fc2: accumulate out[tok][lane*4..+3] over this chunk's hids
        #pragma unroll 2
        for (int hh = 0; hh < 128; hh++) {
            const u64* ap = (const u64*)(s_h + hh * 66 + tokb);
            u64 a[4]; a[0] = ap[0]; a[1] = ap[1]; a[2] = ap[2]; a[3] = ap[3];
            float4 w = *(const float4*)(s_w2 + hh * 128 + lane * 4);
            u64 d[4]; d[0] = dup2(w.x); d[1] = dup2(w.y); d[2] = dup2(w.z); d[3] = dup2(w.w);
            #pragma unroll
            for (int p = 0; p < 4; p++)
                #pragma unroll
                for (int j = 0; j < 4; j++) out[p][j] = fma2(a[p], d[j], out[p][j]);
        }
    }
    // epilogue: gate * (out + b2) -> slot buffer
    float4 b2v = *(const float4*)(b2 + e * C_ + lane * 4);
    #pragma unroll
    for (int p = 0; p < 4; p++) {
        float g0 = s_g[tokb + 2 * p], g1 = s_g[tokb + 2 * p + 1];
        float2 v0 = unpack2(out[p][0]), v1 = unpack2(out[p][1]);
        float2 v2 = unpack2(out[p][2]), v3 = unpack2(out[p][3]);
        size_t sl0 = (size_t)(e * N_ + start + tokb + 2 * p);
        float4 r0 = make_float4(g0 * (v0.x + b2v.x), g0 * (v1.x + b2v.y),
                                g0 * (v2.x + b2v.z), g0 * (v3.x + b2v.w));
        float4 r1 = make_float4(g1 * (v0.y + b2v.x), g1 * (v1.y + b2v.y),
                                g1 * (v2.y + b2v.z), g1 * (v3.y + b2v.w));
        *(float4*)(g_obuf + sl0 * C_ + lane * 4)       = r0;
        *(float4*)(g_obuf + (sl0 + 1) * C_ + lane * 4) = r1;
    }
}

// ------------------- K5: combine slots + residual, NCHW -------------------
__global__ void __launch_bounds__(256) k_combine(const float* __restrict__ x,
                                                 float* __restrict__ dout) {
    __shared__ float s_y[C_ * 66];
    __shared__ int s_sl[128];
    int t = threadIdx.x;
    int n0 = blockIdx.x * 64;
    int b = n0 / HW_; int hw0 = n0 % HW_;
    if (t < 128) s_sl[t] = g_slot[n0 * 2 + t];
    __syncthreads();
    #pragma unroll
    for (int k = 0; k < 8; k++) {
        int lin = t + k * 256; int ts = lin >> 5, c4 = lin & 31;
        int s0 = s_sl[ts * 2], s1 = s_sl[ts * 2 + 1];
        float4 a = *(const float4*)(g_obuf + (size_t)s0 * C_ + c4 * 4);
        float4 bb = *(const float4*)(g_obuf + (size_t)s1 * C_ + c4 * 4);
        s_y[(c4 * 4 + 0) * 66 + ts] = a.x + bb.x;
        s_y[(c4 * 4 + 1) * 66 + ts] = a.y + bb.y;
        s_y[(c4 * 4 + 2) * 66 + ts] = a.z + bb.z;
        s_y[(c4 * 4 + 3) * 66 + ts] = a.w + bb.w;
    }
    __syncthreads();
    size_t base = (size_t)b * C_ * HW_ + hw0;
    for (int k = 0; k < 32; k++) {
        int lin = t + k * 256; int c = lin >> 6, tk = lin & 63;
        size_t idx = base + (size_t)c * HW_ + tk;
        dout[idx] = s_y[c * 66 + tk] + x[idx];
    }
}

// ------------------------------- K6: aux loss -------------------------------
__global__ void k_loss(float* __restrict__ dout, int has_loss) {
    __shared__ float s_imp[E_];
    int t = threadIdx.x;
    int e = t >> 5, lane = t & 31;
    if (t < 128) {
        int cnt = g_cnt[e];
        float s = 0.f;
        for (int i = lane; i < cnt; i += 32) s += g_gate[e * N_ + i];
        #pragma unroll
        for (int o = 16; o > 0; o >>= 1) s += __shfl_xor_sync(0xffffffff, s, o);
        if (lane == 0) s_imp[e] = s;
    }
    __syncthreads();
    if (t == 0 && has_loss) {
        float L[E_], I[E_];
        float mi = 0.f, ml = 0.f;
        for (int k = 0; k < E_; k++) {
            I[k] = s_imp[k]; L[k] = (float)g_cnt[k];
            mi += I[k]; ml += L[k];
        }
        mi *= 0.25f; ml *= 0.25f;
        float vi = 0.f, vl = 0.f;
        for (int k = 0; k < E_; k++) {
            float di = I[k] - mi, dl = L[k] - ml;
            vi += di * di; vl += dl * dl;
        }
        vi *= 0.25f; vl *= 0.25f;
        float loss = 1e-2f * (vi / (mi * mi + 1e-10f) + vl / (ml * ml + 1e-10f));
        dout[NCHW_] = loss;
    }
}

// --------------------------------- launcher ---------------------------------
extern "C" void kernel_launch(void* const* d_in, const int* in_sizes, int n_in,
                              void* d_out, int out_size) {
    const float* x      = (const float*)d_in[0];
    const float* prompt = (const float*)d_in[1];
    const float* w_lin  = (const float*)d_in[2];
    const float* b_lin  = (const float*)d_in[3];
    const float* w_conv = (const float*)d_in[4];
    const float* w_gate = (const float*)d_in[5];
    const float* w1     = (const float*)d_in[6];
    const float* b1     = (const float*)d_in[7];
    const float* w2     = (const float*)d_in[8];
    const float* b2     = (const float*)d_in[9];
    float* out = (float*)d_out;

    cudaFuncSetAttribute(k_expert, cudaFuncAttributeMaxDynamicSharedMemorySize, SM_BYTES);

    k_mean<<<B_ * C_, 256>>>(x);
    k_prep<<<1, 256>>>(prompt, w_lin, b_lin, w_conv);
    k_conv_gate<<<N_ / 64, 256>>>(x, w_gate);
    dim3 ge(N_ / 64, E_);
    k_expert<<<ge, 256, SM_BYTES>>>(w1, b1, w2, b2);
    k_combine<<<N_ / 64, 256>>>(x, out);
    k_loss<<<1, 128>>>(out, (out_size > NCHW_) ? 1 : 0);
}

// round 6
// speedup vs baseline: 1.1809x; 1.1809x over previous
#include <cuda_runtime.h>
#include <math.h>

#define B_     2
#define C_     128
#define HW_    36864
#define N_     73728
#define E_     4
#define HID_   340
#define NCHW_  9437184

typedef unsigned long long u64;

__device__ __forceinline__ u64 fma2(u64 a, u64 b, u64 c) {
    u64 d; asm("fma.rn.f32x2 %0, %1, %2, %3;" : "=l"(d) : "l"(a), "l"(b), "l"(c)); return d;
}
__device__ __forceinline__ u64 dup2(float x) {
    u64 d; asm("mov.b64 %0, {%1, %1};" : "=l"(d) : "f"(x)); return d;
}
__device__ __forceinline__ float2 unpack2(u64 a) {
    float2 r; asm("mov.b64 {%0, %1}, %2;" : "=f"(r.x), "=f"(r.y) : "l"(a)); return r;
}
__device__ __forceinline__ float gelu_exact(float v) {
    return 0.5f * v * (1.0f + erff(v * 0.70710678118654752440f));
}

// ----------------------------- device scratch -----------------------------
__device__ float g_emb[B_ * C_];
__device__ float g_WbT[B_ * C_ * C_];          // [b][c][o]
__device__ float g_ty[(size_t)N_ * C_];        // conv-out tokens [n][c]
__device__ int   g_cnt[E_];
__device__ int   g_tok[E_ * N_];
__device__ float g_gate[E_ * N_];
__device__ int   g_slot[N_ * 2];
__device__ float g_obuf[(size_t)E_ * N_ * C_]; // gated expert outputs per slot

// ----------------------------- K1: channel means -----------------------------
__global__ void k_mean(const float* __restrict__ x) {
    int row = blockIdx.x;                   // b*C + c
    int t = threadIdx.x;
    const float4* xr = (const float4*)(x + (size_t)row * HW_);
    float s = 0.f;
    for (int i = t; i < HW_ / 4; i += 256) {
        float4 v = xr[i];
        s += (v.x + v.y) + (v.z + v.w);
    }
    __shared__ float sm[256];
    sm[t] = s; __syncthreads();
    for (int o = 128; o > 0; o >>= 1) {
        if (t < o) sm[t] += sm[t + o];
        __syncthreads();
    }
    if (t == 0) g_emb[row] = sm[0] * (1.0f / (float)HW_);
}

// --------------------- K2: prompt softmax + fold conv W ---------------------
__global__ void k_prep(const float* __restrict__ prompt, const float* __restrict__ w_lin,
                       const float* __restrict__ b_lin, const float* __restrict__ w_conv) {
    int t = threadIdx.x;
    __shared__ float s_l[B_ * 5], s_pw[B_ * 5], s_sp[B_ * C_];
    if (t < E_) g_cnt[t] = 0;               // reset routing counters every launch
    if (t < B_ * 5) {
        int b = t / 5, p = t % 5;
        float a = b_lin[p];
        for (int c = 0; c < C_; c++) a += g_emb[b * C_ + c] * w_lin[p * C_ + c];
        s_l[t] = a;
    }
    __syncthreads();
    if (t < B_) {
        float m = s_l[t * 5];
        for (int p = 1; p < 5; p++) m = fmaxf(m, s_l[t * 5 + p]);
        float e[5]; float den = 0.f;
        for (int p = 0; p < 5; p++) { e[p] = expf(s_l[t * 5 + p] - m); den += e[p]; }
        for (int p = 0; p < 5; p++) s_pw[t * 5 + p] = e[p] / den;
    }
    __syncthreads();
    {
        int b = t >> 7, c = t & 127;
        float a = 0.f;
        for (int p = 0; p < 5; p++) a += s_pw[b * 5 + p] * prompt[p * C_ + c];
        s_sp[t] = a;
    }
    __syncthreads();
    for (int i = t; i < B_ * C_ * C_; i += 256) {
        int b = i >> 14; int rem = i & 16383; int c = rem >> 7; int o = rem & 127;
        g_WbT[i] = w_conv[o * C_ + c] * s_sp[b * C_ + c];
    }
}

// ---------------- K3: 1x1 conv + gating + top-2 routing scatter ----------------
__global__ void __launch_bounds__(256) k_conv_gate(const float* __restrict__ x,
                                                   const float* __restrict__ w_gate) {
    __shared__ __align__(16) float s_x[C_ * 66];
    __shared__ float s_lg[64 * 4];
    int t = threadIdx.x;
    int n0 = blockIdx.x * 64;
    int b = n0 / HW_; int hw0 = n0 % HW_;
    const float* xb = x + (size_t)b * C_ * HW_ + hw0;
    for (int i = t; i < C_ * 64; i += 256) {
        int c = i >> 6, tk = i & 63;
        s_x[c * 66 + tk] = xb[(size_t)c * HW_ + tk];
    }
    __syncthreads();
    {   // gating logits: thread = (expert, token)
        int e = t >> 6, tk = t & 63;
        float a = 0.f;
        #pragma unroll 8
        for (int c = 0; c < C_; c++) a += s_x[c * 66 + tk] * w_gate[c * 4 + e];
        s_lg[tk * 4 + e] = a;
    }
    __syncthreads();
    if (t < 64) {       // top-2 + softmax + scatter
        float l[4];
        #pragma unroll
        for (int e = 0; e < 4; e++) l[e] = s_lg[t * 4 + e];
        int e0 = 0; float m0 = l[0];
        #pragma unroll
        for (int e = 1; e < 4; e++) if (l[e] > m0) { m0 = l[e]; e0 = e; }
        int e1 = (e0 == 0) ? 1 : 0; float m1 = l[e1];
        #pragma unroll
        for (int e = 0; e < 4; e++) if (e != e0 && l[e] > m1) { m1 = l[e]; e1 = e; }
        float ex = expf(m1 - m0);
        float g0 = 1.0f / (1.0f + ex);
        float g1 = ex * g0;
        int n = n0 + t;
        int p0 = atomicAdd(&g_cnt[e0], 1);
        g_tok[e0 * N_ + p0] = n; g_gate[e0 * N_ + p0] = g0;
        g_slot[n * 2 + 0] = e0 * N_ + p0;
        int p1 = atomicAdd(&g_cnt[e1], 1);
        g_tok[e1 * N_ + p1] = n; g_gate[e1 * N_ + p1] = g1;
        g_slot[n * 2 + 1] = e1 * N_ + p1;
    }
    // conv GEMM: ty[tok][o] = sum_c s_x[c][tok] * WbT[b][c][o]
    int warp = t >> 5, lane = t & 31, tokb = warp * 8;
    u64 acc[4][4];
    #pragma unroll
    for (int p = 0; p < 4; p++)
        #pragma unroll
        for (int j = 0; j < 4; j++) acc[p][j] = 0ull;
    const float* wr = g_WbT + b * C_ * C_ + lane * 4;
    #pragma unroll 4
    for (int c = 0; c < C_; c++) {
        float4 w = *(const float4*)(wr + c * C_);
        const u64* ap = (const u64*)(s_x + c * 66 + tokb);
        u64 a[4]; a[0] = ap[0]; a[1] = ap[1]; a[2] = ap[2]; a[3] = ap[3];
        u64 d[4]; d[0] = dup2(w.x); d[1] = dup2(w.y); d[2] = dup2(w.z); d[3] = dup2(w.w);
        #pragma unroll
        for (int p = 0; p < 4; p++)
            #pragma unroll
            for (int j = 0; j < 4; j++) acc[p][j] = fma2(a[p], d[j], acc[p][j]);
    }
    #pragma unroll
    for (int p = 0; p < 4; p++) {
        float2 v0 = unpack2(acc[p][0]), v1 = unpack2(acc[p][1]);
        float2 v2 = unpack2(acc[p][2]), v3 = unpack2(acc[p][3]);
        size_t tok0 = (size_t)(n0 + tokb + 2 * p);
        *(float4*)(g_ty + tok0 * C_ + lane * 4)       = make_float4(v0.x, v1.x, v2.x, v3.x);
        *(float4*)(g_ty + (tok0 + 1) * C_ + lane * 4) = make_float4(v0.y, v1.y, v2.y, v3.y);
    }
}

// ---------------- K4: fused expert fc1 + gelu + fc2 (routed) ----------------
// smem: s_ty[128][66] | s_h[128][66] | s_g[64] | s_tk[64]  => 68,096 B
// Weights are read directly via LDG (L1/L2 broadcast across warps/CTAs).
#define SMX_H     8448
#define SMX_G     16896
#define SMX_TK    16960
#define SMX_BYTES (17024 * 4)

__global__ void __launch_bounds__(256, 2) k_expert(const float* __restrict__ w1,
                                                   const float* __restrict__ b1,
                                                   const float* __restrict__ w2,
                                                   const float* __restrict__ b2) {
    extern __shared__ __align__(16) float sm[];
    float* s_ty = sm;
    float* s_h  = sm + SMX_H;
    float* s_g  = sm + SMX_G;
    int*   s_tk = (int*)(sm + SMX_TK);

    int e = blockIdx.y;
    int cnt = g_cnt[e];
    int start = blockIdx.x * 64;
    if (start >= cnt) return;
    int t = threadIdx.x;
    if (t < 64) {
        int idx = start + t;
        if (idx < cnt) { s_tk[t] = g_tok[e * N_ + idx]; s_g[t] = g_gate[e * N_ + idx]; }
        else           { s_tk[t] = 0;                   s_g[t] = 0.f; }
    }
    __syncthreads();
    // gather ty tile, transposed [c][slot]
    #pragma unroll
    for (int k = 0; k < 8; k++) {
        int lin = t + k * 256; int slot = lin >> 5, c4 = lin & 31;
        int tok = s_tk[slot];
        float4 v = *(const float4*)(g_ty + (size_t)tok * C_ + c4 * 4);
        s_ty[(c4 * 4 + 0) * 66 + slot] = v.x;
        s_ty[(c4 * 4 + 1) * 66 + slot] = v.y;
        s_ty[(c4 * 4 + 2) * 66 + slot] = v.z;
        s_ty[(c4 * 4 + 3) * 66 + slot] = v.w;
    }
    int warp = t >> 5, lane = t & 31, tokb = warp * 8;
    const float* w1e = w1 + e * C_ * HID_;
    const float* w2e = w2 + e * HID_ * C_;
    u64 out[4][4];
    #pragma unroll
    for (int p = 0; p < 4; p++)
        #pragma unroll
        for (int j = 0; j < 4; j++) out[p][j] = 0ull;

    int h4 = lane * 4;
    for (int ch = 0; ch < 3; ch++) {
        int hb = ch * 128;
        bool hv = (hb + h4) < HID_;              // lane block fully valid (340-256 = 84 = 21*4)
        int hoff = hv ? (hb + h4) : 0;           // safe dummy offset when invalid
        __syncthreads();                          // prev fc2 done with s_h; (ch=0) gather done

        // ---- fc1: h[hid][tok] for this chunk ----
        u64 acc[4][4];
        {
            float4 b1v = *(const float4*)(b1 + e * HID_ + hoff);
            u64 d0 = dup2(b1v.x), d1 = dup2(b1v.y), d2 = dup2(b1v.z), d3 = dup2(b1v.w);
            #pragma unroll
            for (int p = 0; p < 4; p++) { acc[p][0] = d0; acc[p][1] = d1; acc[p][2] = d2; acc[p][3] = d3; }
        }
        {
            const float* wp = w1e + hoff;
            const float* ap = s_ty + tokb;
            #pragma unroll 2
            for (int c = 0; c < C_; c++) {
                float4 w = *(const float4*)wp; wp += HID_;
                const u64* a8 = (const u64*)ap; ap += 66;
                u64 a0 = a8[0], a1 = a8[1], a2 = a8[2], a3 = a8[3];
                u64 d0 = dup2(w.x), d1 = dup2(w.y), d2 = dup2(w.z), d3 = dup2(w.w);
                acc[0][0] = fma2(a0, d0, acc[0][0]); acc[0][1] = fma2(a0, d1, acc[0][1]);
                acc[0][2] = fma2(a0, d2, acc[0][2]); acc[0][3] = fma2(a0, d3, acc[0][3]);
                acc[1][0] = fma2(a1, d0, acc[1][0]); acc[1][1] = fma2(a1, d1, acc[1][1]);
                acc[1][2] = fma2(a1, d2, acc[1][2]); acc[1][3] = fma2(a1, d3, acc[1][3]);
                acc[2][0] = fma2(a2, d0, acc[2][0]); acc[2][1] = fma2(a2, d1, acc[2][1]);
                acc[2][2] = fma2(a2, d2, acc[2][2]); acc[2][3] = fma2(a2, d3, acc[2][3]);
                acc[3][0] = fma2(a3, d0, acc[3][0]); acc[3][1] = fma2(a3, d1, acc[3][1]);
                acc[3][2] = fma2(a3, d2, acc[3][2]); acc[3][3] = fma2(a3, d3, acc[3][3]);
            }
        }
        // gelu + store h transposed [hid][tok] (rows >= hmax never read)
        #pragma unroll
        for (int p = 0; p < 4; p++)
            #pragma unroll
            for (int j = 0; j < 4; j++) {
                float2 v = unpack2(acc[p][j]);
                v.x = gelu_exact(v.x); v.y = gelu_exact(v.y);
                *(float2*)(s_h + (h4 + j) * 66 + tokb + 2 * p) = v;
            }
        __syncthreads();

        // ---- fc2: accumulate out over this chunk's valid hids ----
        int hmax = HID_ - hb; if (hmax > 128) hmax = 128;
        const float* wq = w2e + hb * C_ + lane * 4;
        const float* hp = s_h + tokb;
        #pragma unroll 2
        for (int hh = 0; hh < hmax; hh++) {
            float4 w = *(const float4*)wq; wq += C_;
            const u64* a8 = (const u64*)hp; hp += 66;
            u64 a0 = a8[0], a1 = a8[1], a2 = a8[2], a3 = a8[3];
            u64 d0 = dup2(w.x), d1 = dup2(w.y), d2 = dup2(w.z), d3 = dup2(w.w);
            out[0][0] = fma2(a0, d0, out[0][0]); out[0][1] = fma2(a0, d1, out[0][1]);
            out[0][2] = fma2(a0, d2, out[0][2]); out[0][3] = fma2(a0, d3, out[0][3]);
            out[1][0] = fma2(a1, d0, out[1][0]); out[1][1] = fma2(a1, d1, out[1][1]);
            out[1][2] = fma2(a1, d2, out[1][2]); out[1][3] = fma2(a1, d3, out[1][3]);
            out[2][0] = fma2(a2, d0, out[2][0]); out[2][1] = fma2(a2, d1, out[2][1]);
            out[2][2] = fma2(a2, d2, out[2][2]); out[2][3] = fma2(a2, d3, out[2][3]);
            out[3][0] = fma2(a3, d0, out[3][0]); out[3][1] = fma2(a3, d1, out[3][1]);
            out[3][2] = fma2(a3, d2, out[3][2]); out[3][3] = fma2(a3, d3, out[3][3]);
        }
    }
    // epilogue: gate * (out + b2) -> slot buffer
    float4 b2v = *(const float4*)(b2 + e * C_ + lane * 4);
    #pragma unroll
    for (int p = 0; p < 4; p++) {
        float g0 = s_g[tokb + 2 * p], g1 = s_g[tokb + 2 * p + 1];
        float2 v0 = unpack2(out[p][0]), v1 = unpack2(out[p][1]);
        float2 v2 = unpack2(out[p][2]), v3 = unpack2(out[p][3]);
        size_t sl0 = (size_t)(e * N_ + start + tokb + 2 * p);
        float4 r0 = make_float4(g0 * (v0.x + b2v.x), g0 * (v1.x + b2v.y),
                                g0 * (v2.x + b2v.z), g0 * (v3.x + b2v.w));
        float4 r1 = make_float4(g1 * (v0.y + b2v.x), g1 * (v1.y + b2v.y),
                                g1 * (v2.y + b2v.z), g1 * (v3.y + b2v.w));
        *(float4*)(g_obuf + sl0 * C_ + lane * 4)       = r0;
        *(float4*)(g_obuf + (sl0 + 1) * C_ + lane * 4) = r1;
    }
}

// ------------------- K5: combine slots + residual, NCHW -------------------
__global__ void __launch_bounds__(256) k_combine(const float* __restrict__ x,
                                                 float* __restrict__ dout) {
    __shared__ float s_y[C_ * 66];
    __shared__ int s_sl[128];
    int t = threadIdx.x;
    int n0 = blockIdx.x * 64;
    int b = n0 / HW_; int hw0 = n0 % HW_;
    if (t < 128) s_sl[t] = g_slot[n0 * 2 + t];
    __syncthreads();
    #pragma unroll
    for (int k = 0; k < 8; k++) {
        int lin = t + k * 256; int ts = lin >> 5, c4 = lin & 31;
        int s0 = s_sl[ts * 2], s1 = s_sl[ts * 2 + 1];
        float4 a = *(const float4*)(g_obuf + (size_t)s0 * C_ + c4 * 4);
        float4 bb = *(const float4*)(g_obuf + (size_t)s1 * C_ + c4 * 4);
        s_y[(c4 * 4 + 0) * 66 + ts] = a.x + bb.x;
        s_y[(c4 * 4 + 1) * 66 + ts] = a.y + bb.y;
        s_y[(c4 * 4 + 2) * 66 + ts] = a.z + bb.z;
        s_y[(c4 * 4 + 3) * 66 + ts] = a.w + bb.w;
    }
    __syncthreads();
    size_t base = (size_t)b * C_ * HW_ + hw0;
    for (int k = 0; k < 32; k++) {
        int lin = t + k * 256; int c = lin >> 6, tk = lin & 63;
        size_t idx = base + (size_t)c * HW_ + tk;
        dout[idx] = s_y[c * 66 + tk] + x[idx];
    }
}

// ------------------------------- K6: aux loss -------------------------------
__global__ void k_loss(float* __restrict__ dout, int has_loss) {
    __shared__ float s_imp[E_];
    int t = threadIdx.x;
    int e = t >> 5, lane = t & 31;
    if (t < 128) {
        int cnt = g_cnt[e];
        float s = 0.f;
        for (int i = lane; i < cnt; i += 32) s += g_gate[e * N_ + i];
        #pragma unroll
        for (int o = 16; o > 0; o >>= 1) s += __shfl_xor_sync(0xffffffff, s, o);
        if (lane == 0) s_imp[e] = s;
    }
    __syncthreads();
    if (t == 0 && has_loss) {
        float L[E_], I[E_];
        float mi = 0.f, ml = 0.f;
        for (int k = 0; k < E_; k++) {
            I[k] = s_imp[k]; L[k] = (float)g_cnt[k];
            mi += I[k]; ml += L[k];
        }
        mi *= 0.25f; ml *= 0.25f;
        float vi = 0.f, vl = 0.f;
        for (int k = 0; k < E_; k++) {
            float di = I[k] - mi, dl = L[k] - ml;
            vi += di * di; vl += dl * dl;
        }
        vi *= 0.25f; vl *= 0.25f;
        float loss = 1e-2f * (vi / (mi * mi + 1e-10f) + vl / (ml * ml + 1e-10f));
        dout[NCHW_] = loss;
    }
}

// --------------------------------- launcher ---------------------------------
extern "C" void kernel_launch(void* const* d_in, const int* in_sizes, int n_in,
                              void* d_out, int out_size) {
    const float* x      = (const float*)d_in[0];
    const float* prompt = (const float*)d_in[1];
    const float* w_lin  = (const float*)d_in[2];
    const float* b_lin  = (const float*)d_in[3];
    const float* w_conv = (const float*)d_in[4];
    const float* w_gate = (const float*)d_in[5];
    const float* w1     = (const float*)d_in[6];
    const float* b1     = (const float*)d_in[7];
    const float* w2     = (const float*)d_in[8];
    const float* b2     = (const float*)d_in[9];
    float* out = (float*)d_out;

    cudaFuncSetAttribute(k_expert, cudaFuncAttributeMaxDynamicSharedMemorySize, SMX_BYTES);

    k_mean<<<B_ * C_, 256>>>(x);
    k_prep<<<1, 256>>>(prompt, w_lin, b_lin, w_conv);
    k_conv_gate<<<N_ / 64, 256>>>(x, w_gate);
    dim3 ge(N_ / 64, E_);
    k_expert<<<ge, 256, SMX_BYTES>>>(w1, b1, w2, b2);
    k_combine<<<N_ / 64, 256>>>(x, out);
    k_loss<<<1, 128>>>(out, (out_size > NCHW_) ? 1 : 0);
}